// round 14
// baseline (speedup 1.0000x reference)
#include <cuda_runtime.h>
#include <cuda_fp16.h>
#include <math.h>
#include <cstdint>

#define NN   100000
#define NE   1600000
#define HD   64
#define NG   256
#define NLAY 3
#define G3   192   // 3*HD

#define SCAN_TPB  512
#define SCAN_BLKS ((NN + SCAN_TPB - 1) / SCAN_TPB)   // 196

// ---------------- scratch (device globals; no allocation allowed) -------------
__device__ float  g_h0[NN * HD];
__device__ float  g_h1[NN * HD];
__device__ __half g_xh[NN * HD];      // fp16 mirror of x
__device__ __half g_hh0[NN * HD];     // fp16 mirror of h (ping/pong)
__device__ __half g_hh1[NN * HD];
__device__ int   g_rowptr[NN + 1];
__device__ int   g_cnt[NN];
__device__ int   g_aggv[SCAN_BLKS];
__device__ int   g_incv[SCAN_BLKS];
__device__ int   g_flag[SCAN_BLKS];
__device__ int   g_col[NE];
__device__ __half g_wf[NLAY * G3 * HD];   // fp16 fused W@Wih^T, [l][gate][c]
__device__ __half g_wh[G3 * HD];          // fp16 W_hh

// ---------------- ptx helpers (baseline ISA only: ldmatrix + mma.sync) --------
__device__ __forceinline__ uint32_t smem_u32(const void* p) {
    uint32_t a;
    asm("{ .reg .u64 t; cvta.to.shared.u64 t, %1; cvt.u32.u64 %0, t; }" : "=r"(a) : "l"(p));
    return a;
}
__device__ __forceinline__ void ldm4(uint32_t* r, uint32_t addr) {
    asm volatile("ldmatrix.sync.aligned.m8n8.x4.shared.b16 {%0,%1,%2,%3}, [%4];"
                 : "=r"(r[0]), "=r"(r[1]), "=r"(r[2]), "=r"(r[3]) : "r"(addr));
}
__device__ __forceinline__ void mma16816(float* d, const uint32_t* a, const uint32_t* b) {
    asm volatile(
        "mma.sync.aligned.m16n8k16.row.col.f32.f16.f16.f32 "
        "{%0,%1,%2,%3}, {%4,%5,%6,%7}, {%8,%9}, {%0,%1,%2,%3};"
        : "+f"(d[0]), "+f"(d[1]), "+f"(d[2]), "+f"(d[3])
        : "r"(a[0]), "r"(a[1]), "r"(a[2]), "r"(a[3]), "r"(b[0]), "r"(b[1]));
}

// ---------------- prep: zero state + weight fusion + fp16 casts ----------------
__global__ void prep_k(const float* __restrict__ W, const float* __restrict__ Wih,
                       const float* __restrict__ Whh, const float* __restrict__ x,
                       float* __restrict__ out) {
    int tid = blockIdx.x * blockDim.x + threadIdx.x;
    if (tid < NN) g_cnt[tid] = 0;
    if (tid < SCAN_BLKS) g_flag[tid] = 0;
    if (tid < NG * HD) out[tid] = 0.f;
    if (tid < NN * HD) g_xh[tid] = __float2half(x[tid]);
    if (tid < NLAY * G3 * HD) {
        int c = tid & (HD - 1);
        int j = (tid >> 6) % G3;
        int l = tid / (G3 * HD);
        const float* wrow = W + (l * HD + c) * HD;
        const float* irow = Wih + j * HD;
        float s = 0.f;
#pragma unroll
        for (int k = 0; k < HD; k++) s = fmaf(wrow[k], irow[k], s);
        g_wf[tid] = __float2half(s);
    }
    if (tid < G3 * HD) g_wh[tid] = __float2half(Whh[tid]);
}

// ---------------- CSR build ----------------------------------------------------
__global__ void hist_k(const int* __restrict__ dst) {
    int e = blockIdx.x * blockDim.x + threadIdx.x;
    if (e < NE) atomicAdd(&g_cnt[dst[e]], 1);
}

// single-pass decoupled-lookback scan (196 blocks, all resident)
__global__ void scan_k() {
    __shared__ int ss[SCAN_TPB];
    __shared__ int s_excl;
    int t = threadIdx.x, b = blockIdx.x;
    int i = b * SCAN_TPB + t;
    int orig = (i < NN) ? g_cnt[i] : 0;
    ss[t] = orig;
    __syncthreads();
#pragma unroll
    for (int off = 1; off < SCAN_TPB; off <<= 1) {
        int u = (t >= off) ? ss[t - off] : 0;
        __syncthreads();
        ss[t] += u;
        __syncthreads();
    }
    int incl = ss[t];
    int total = ss[SCAN_TPB - 1];

    if (t == 0) {
        if (b == 0) {
            *(volatile int*)&g_incv[0] = total;
            __threadfence();
            *(volatile int*)&g_flag[0] = 2;
            s_excl = 0;
        } else {
            *(volatile int*)&g_aggv[b] = total;
            __threadfence();
            *(volatile int*)&g_flag[b] = 1;
        }
    }
    if (b > 0 && t < 32) {
        int running = 0;
        for (int base = b - 1; base >= 0; base -= 32) {
            int idx = base - t;
            int f;
            do {
                f = (idx >= 0) ? *(volatile int*)&g_flag[idx] : 2;
            } while (__any_sync(0xffffffffu, f == 0));
            __threadfence();
            int val = 0;
            if (idx >= 0)
                val = (f == 2) ? *(volatile int*)&g_incv[idx] : *(volatile int*)&g_aggv[idx];
            unsigned m = __ballot_sync(0xffffffffu, (f == 2) && idx >= 0);
            int firstP = m ? (__ffs(m) - 1) : 32;
            int contrib = (t <= firstP && idx >= 0) ? val : 0;
#pragma unroll
            for (int o = 16; o; o >>= 1) contrib += __shfl_down_sync(0xffffffffu, contrib, o);
            contrib = __shfl_sync(0xffffffffu, contrib, 0);
            running += contrib;
            if (m) break;
        }
        if (t == 0) {
            *(volatile int*)&g_incv[b] = running + total;
            __threadfence();
            *(volatile int*)&g_flag[b] = 2;
            s_excl = running;
        }
    }
    __syncthreads();
    int excl = s_excl + incl - orig;
    if (i < NN) {
        g_rowptr[i] = excl;
        g_cnt[i] = excl;   // scatter cursor
    }
    if (i == 0) g_rowptr[NN] = NE;
}

__global__ void scatter_k(const int* __restrict__ src, const int* __restrict__ dst) {
    int e = blockIdx.x * blockDim.x + threadIdx.x;
    if (e < NE) {
        int p = atomicAdd(&g_cnt[dst[e]], 1);
        g_col[p] = src[e];
    }
}

// ---------------- fused gather + GRU (fp16 mma.sync), 2 blocks/SM --------------
// Phase 1 per tile: each warp gathers 8 node-rows (4 edges/step, uint4 lanes,
// fp32 accum) straight into the SMEM A tile as fp16.  Phase 2: fp16 GEMMs.
// With 2 resident blocks, one block's gather overlaps the other's MMA.
// SMEM: A 9216 + H 9216 + Wf 27648 + Wh 27648 = 73728 bytes (x2 = 147KB)
#define ROWB 144
#define OFF_A  0
#define OFF_H  9216
#define OFF_WF 18432
#define OFF_WH 46080
#define GRU_SMEM 73728
#define NTILES ((NN + 63) / 64)   // 1563
#define GRU_GRID 296
#define GRU_TPB 256

#define IDX(p, t, h) ((((p) * 2 + (t)) * 2 + (h)) * 4)

__global__ void __launch_bounds__(GRU_TPB, 2) gru_mma(
    const __half* __restrict__ hinh,
    const float* __restrict__ hin, float* __restrict__ hout,
    __half* __restrict__ houth,
    const __half* __restrict__ wf,
    const float* __restrict__ bih, const float* __restrict__ bhh) {
    extern __shared__ __align__(16) char sm[];
    int tid = threadIdx.x, wid = tid >> 5, lane = tid & 31;

    // ---- stage weights ONCE (fp16, [gate][c] rows) ----
    for (int i = tid; i < G3 * 16; i += GRU_TPB) {
        int r = i >> 4, c8 = i & 15;
        uint32_t off = r * ROWB + c8 * 8;
        *(uint2*)(sm + OFF_WF + off) = *(const uint2*)(wf + r * 64 + c8 * 4);
        *(uint2*)(sm + OFF_WH + off) = *(const uint2*)(g_wh + r * 64 + c8 * 4);
    }

    uint32_t sbase = smem_u32(sm);
    int mrow0 = (wid & 3) * 16;        // 4 M-stripes of 16 rows
    int d0 = (wid >> 2) * 32;          // 2 feature groups of 32
    uint32_t aOff = (mrow0 + (lane & 15)) * ROWB + (lane >> 4) * 16;
    uint32_t bRow = (lane >> 4) * 8 + (lane & 7);
    uint32_t bCol = ((lane >> 3) & 1) * 16;

    const uint4* hh4 = (const uint4*)hinh;
    int gc = lane & 7, ges = lane >> 3;   // gather: feature chunk / edge slot

    for (int tile = blockIdx.x; tile < NTILES; tile += GRU_GRID) {
        int n0 = tile * 64;
        __syncthreads();   // previous tile's MMA readers done

        // ---- phase 1a: gather 8 node-rows per warp into SMEM A (fp16) ----
#pragma unroll 1
        for (int r = 0; r < 8; r++) {
            int row = wid * 8 + r;
            int node = n0 + row;
            float acc[8];
#pragma unroll
            for (int k = 0; k < 8; k++) acc[k] = 0.f;
            if (node < NN) {
                int beg = g_rowptr[node], end = g_rowptr[node + 1];
#pragma unroll 2
                for (int e = beg + ges; e < end; e += 4) {
                    int s = g_col[e];
                    uint4 v = hh4[(size_t)s * 8 + gc];
                    const __half2* p = (const __half2*)&v;
#pragma unroll
                    for (int k = 0; k < 4; k++) {
                        float2 f = __half22float2(p[k]);
                        acc[2 * k]     += f.x;
                        acc[2 * k + 1] += f.y;
                    }
                }
            }
#pragma unroll
            for (int k = 0; k < 8; k++) {
                acc[k] += __shfl_xor_sync(0xffffffffu, acc[k], 8);
                acc[k] += __shfl_xor_sync(0xffffffffu, acc[k], 16);
            }
            if (lane < 8) {
                __half2 h01 = __floats2half2_rn(acc[0], acc[1]);
                __half2 h23 = __floats2half2_rn(acc[2], acc[3]);
                __half2 h45 = __floats2half2_rn(acc[4], acc[5]);
                __half2 h67 = __floats2half2_rn(acc[6], acc[7]);
                uint4 o;
                o.x = *(uint32_t*)&h01; o.y = *(uint32_t*)&h23;
                o.z = *(uint32_t*)&h45; o.w = *(uint32_t*)&h67;
                *(uint4*)(sm + OFF_A + row * ROWB + lane * 16) = o;
            }
        }

        // ---- phase 1b: stage H (pure uint4 copy, fp16 already) ----
        for (int i = tid; i < 64 * 8; i += GRU_TPB) {
            int t = i >> 3, c = i & 7;
            uint4 vh = make_uint4(0u, 0u, 0u, 0u);
            if (n0 + t < NN) vh = ((const uint4*)(hinh + (size_t)(n0 + t) * HD))[c];
            *(uint4*)(sm + OFF_H + t * ROWB + c * 16) = vh;
        }
        __syncthreads();

        // ---- phase 2: single-product fp16 GEMMs, 3 gate planes x 2 n16 ----
        float dgi[48], dgh[48];
#pragma unroll
        for (int q = 0; q < 48; q++) { dgi[q] = 0.f; dgh[q] = 0.f; }

#pragma unroll
        for (int ks = 0; ks < 4; ks++) {
            uint32_t kb = ks * 32;
            uint32_t aF[4], hF[4];
            ldm4(aF, sbase + OFF_A + aOff + kb);
            ldm4(hF, sbase + OFF_H + aOff + kb);
#pragma unroll
            for (int p = 0; p < 3; p++) {
#pragma unroll
                for (int t = 0; t < 2; t++) {
                    uint32_t bo = (p * 64 + d0 + t * 16 + bRow) * ROWB + bCol + kb;
                    int I = IDX(p, t, 0);
                    uint32_t bF[4], bG[4];
                    ldm4(bF, sbase + OFF_WF + bo);
                    ldm4(bG, sbase + OFF_WH + bo);
                    mma16816(dgi + I,     aF, bF);
                    mma16816(dgi + I + 4, aF, bF + 2);
                    mma16816(dgh + I,     hF, bG);
                    mma16816(dgh + I + 4, hF, bG + 2);
                }
            }
        }

        // ---- phase 3: register epilogue (biases + fp32 h_prev, L1/L2-hot) ----
#pragma unroll
        for (int t = 0; t < 2; t++)
#pragma unroll
            for (int h = 0; h < 2; h++) {
                int dE = d0 + t * 16 + h * 8 + (lane & 3) * 2;
                float2 bi_r = *(const float2*)(bih + dE);
                float2 bh_r = *(const float2*)(bhh + dE);
                float2 bi_z = *(const float2*)(bih + 64 + dE);
                float2 bh_z = *(const float2*)(bhh + 64 + dE);
                float2 bi_n = *(const float2*)(bih + 128 + dE);
                float2 bh_n = *(const float2*)(bhh + 128 + dE);
                float brz[2] = {bi_r.x + bh_r.x, bi_r.y + bh_r.y};
                float bzz[2] = {bi_z.x + bh_z.x, bi_z.y + bh_z.y};
                float bnn[2] = {bi_n.x, bi_n.y};
                float bhn[2] = {bh_n.x, bh_n.y};
#pragma unroll
                for (int rh = 0; rh < 2; rh++) {
                    int row = mrow0 + (lane >> 2) + rh * 8;
                    if (n0 + row >= NN) continue;
                    float2 hpv = *(const float2*)(hin + (size_t)(n0 + row) * HD + dE);
                    float hpa[2] = {hpv.x, hpv.y};
                    float outv[2];
#pragma unroll
                    for (int j = 0; j < 2; j++) {
                        int q = rh * 2 + j;
                        float ar = dgi[IDX(0, t, h) + q] + dgh[IDX(0, t, h) + q] + brz[j];
                        float az = dgi[IDX(1, t, h) + q] + dgh[IDX(1, t, h) + q] + bzz[j];
                        float r = 1.f / (1.f + __expf(-ar));
                        float z = 1.f / (1.f + __expf(-az));
                        float xarg = dgi[IDX(2, t, h) + q] + bnn[j] +
                                     r * (dgh[IDX(2, t, h) + q] + bhn[j]);
                        float nn = 1.f - 2.f / (__expf(2.f * xarg) + 1.f);  // tanh
                        outv[j] = (1.f - z) * nn + z * hpa[j];
                    }
                    size_t gidx = (size_t)(n0 + row) * HD + dE;
                    *(float2*)(hout + gidx) = make_float2(outv[0], outv[1]);
                    *(__half2*)(houth + gidx) = __floats2half2_rn(outv[0], outv[1]);
                }
            }
    }
}

// ---------------- pooling: batch sorted -> run-length accumulate ---------------
__global__ void pool_k(const float* __restrict__ h, const int* __restrict__ batch,
                       float* __restrict__ out) {
    int d = threadIdx.x;
    int n0 = blockIdx.x * 128;
    int nend = min(n0 + 128, NN);
    if (n0 >= NN) return;
    float acc = 0.f;
    int cur = batch[n0];
    for (int n = n0; n < nend; n++) {
        int b = batch[n];
        if (b != cur) {
            atomicAdd(&out[cur * HD + d], acc);
            acc = 0.f;
            cur = b;
        }
        acc += h[(size_t)n * HD + d];
    }
    atomicAdd(&out[cur * HD + d], acc);
}

// ---------------- launch --------------------------------------------------------
extern "C" void kernel_launch(void* const* d_in, const int* in_sizes, int n_in,
                              void* d_out, int out_size) {
    const float* x    = (const float*)d_in[0];
    const int*   ei   = (const int*)d_in[1];
    const int*   batch= (const int*)d_in[2];
    const float* W    = (const float*)d_in[3];
    const float* Wih  = (const float*)d_in[4];
    const float* Whh  = (const float*)d_in[5];
    const float* bih  = (const float*)d_in[6];
    const float* bhh  = (const float*)d_in[7];
    float* out = (float*)d_out;
    const int* src = ei;
    const int* dst = ei + NE;

    void *h0p, *h1p, *xhp, *hh0p, *hh1p, *wfp;
    cudaGetSymbolAddress(&h0p, g_h0);
    cudaGetSymbolAddress(&h1p, g_h1);
    cudaGetSymbolAddress(&xhp, g_xh);
    cudaGetSymbolAddress(&hh0p, g_hh0);
    cudaGetSymbolAddress(&hh1p, g_hh1);
    cudaGetSymbolAddress(&wfp, g_wf);

    cudaFuncSetAttribute(gru_mma, cudaFuncAttributeMaxDynamicSharedMemorySize, GRU_SMEM);

    prep_k<<<(NN * HD + 255) / 256, 256>>>(W, Wih, Whh, x, out);
    hist_k<<<(NE + 255) / 256, 256>>>(dst);
    scan_k<<<SCAN_BLKS, SCAN_TPB>>>();
    scatter_k<<<(NE + 255) / 256, 256>>>(src, dst);

    const float*  hin  = x;
    const __half* hinh = (const __half*)xhp;
    for (int l = 0; l < NLAY; l++) {
        float*  hout  = (l & 1) ? (float*)h0p : (float*)h1p;
        __half* houth = (l & 1) ? (__half*)hh0p : (__half*)hh1p;
        gru_mma<<<GRU_GRID, GRU_TPB, GRU_SMEM>>>(
            hinh, hin, hout, houth,
            (const __half*)wfp + (size_t)l * G3 * HD,
            bih, bhh);
        hin = hout;
        hinh = houth;
    }
    pool_k<<<(NN + 127) / 128, 64>>>(hin, batch, out);
}

// round 15
// speedup vs baseline: 1.5081x; 1.5081x over previous
#include <cuda_runtime.h>
#include <cuda_fp16.h>
#include <math.h>
#include <cstdint>

#define NN   100000
#define NE   1600000
#define HD   64
#define NG   256
#define NLAY 3
#define G3   192   // 3*HD

#define SCAN_TPB  512
#define SCAN_BLKS ((NN + SCAN_TPB - 1) / SCAN_TPB)   // 196

// ---------------- scratch (device globals; no allocation allowed) -------------
__device__ float  g_h0[NN * HD];
__device__ float  g_h1[NN * HD];
__device__ __half g_xh[NN * HD];      // fp16 mirror of x
__device__ __half g_hh0[NN * HD];     // fp16 mirror of h (ping/pong)
__device__ __half g_hh1[NN * HD];
__device__ __half g_aggh[NN * HD];    // fp16 aggregation result
__device__ int   g_rowptr[NN + 1];
__device__ int   g_cnt[NN];
__device__ int   g_aggv[SCAN_BLKS];
__device__ int   g_incv[SCAN_BLKS];
__device__ int   g_flag[SCAN_BLKS];
__device__ int   g_col[NE];
__device__ __half g_wf[NLAY * G3 * HD];   // fp16 fused W@Wih^T, [l][gate][c]
__device__ __half g_wh[G3 * HD];          // fp16 W_hh

// ---------------- ptx helpers (baseline ISA only: ldmatrix + mma.sync) --------
__device__ __forceinline__ uint32_t smem_u32(const void* p) {
    uint32_t a;
    asm("{ .reg .u64 t; cvta.to.shared.u64 t, %1; cvt.u32.u64 %0, t; }" : "=r"(a) : "l"(p));
    return a;
}
__device__ __forceinline__ void ldm4(uint32_t* r, uint32_t addr) {
    asm volatile("ldmatrix.sync.aligned.m8n8.x4.shared.b16 {%0,%1,%2,%3}, [%4];"
                 : "=r"(r[0]), "=r"(r[1]), "=r"(r[2]), "=r"(r[3]) : "r"(addr));
}
__device__ __forceinline__ void mma16816(float* d, const uint32_t* a, const uint32_t* b) {
    asm volatile(
        "mma.sync.aligned.m16n8k16.row.col.f32.f16.f16.f32 "
        "{%0,%1,%2,%3}, {%4,%5,%6,%7}, {%8,%9}, {%0,%1,%2,%3};"
        : "+f"(d[0]), "+f"(d[1]), "+f"(d[2]), "+f"(d[3])
        : "r"(a[0]), "r"(a[1]), "r"(a[2]), "r"(a[3]), "r"(b[0]), "r"(b[1]));
}

// ---------------- prep: zero state + weight fusion + fp16 casts ----------------
__global__ void prep_k(const float* __restrict__ W, const float* __restrict__ Wih,
                       const float* __restrict__ Whh, const float* __restrict__ x,
                       float* __restrict__ out) {
    int tid = blockIdx.x * blockDim.x + threadIdx.x;
    if (tid < NN) g_cnt[tid] = 0;
    if (tid < SCAN_BLKS) g_flag[tid] = 0;
    if (tid < NG * HD) out[tid] = 0.f;
    if (tid < NN * HD) g_xh[tid] = __float2half(x[tid]);
    if (tid < NLAY * G3 * HD) {
        int c = tid & (HD - 1);
        int j = (tid >> 6) % G3;
        int l = tid / (G3 * HD);
        const float* wrow = W + (l * HD + c) * HD;
        const float* irow = Wih + j * HD;
        float s = 0.f;
#pragma unroll
        for (int k = 0; k < HD; k++) s = fmaf(wrow[k], irow[k], s);
        g_wf[tid] = __float2half(s);
    }
    if (tid < G3 * HD) g_wh[tid] = __float2half(Whh[tid]);
}

// ---------------- CSR build ----------------------------------------------------
__global__ void hist_k(const int* __restrict__ dst) {
    int e = blockIdx.x * blockDim.x + threadIdx.x;
    if (e < NE) atomicAdd(&g_cnt[dst[e]], 1);
}

// single-pass decoupled-lookback scan (196 blocks, all resident)
__global__ void scan_k() {
    __shared__ int ss[SCAN_TPB];
    __shared__ int s_excl;
    int t = threadIdx.x, b = blockIdx.x;
    int i = b * SCAN_TPB + t;
    int orig = (i < NN) ? g_cnt[i] : 0;
    ss[t] = orig;
    __syncthreads();
#pragma unroll
    for (int off = 1; off < SCAN_TPB; off <<= 1) {
        int u = (t >= off) ? ss[t - off] : 0;
        __syncthreads();
        ss[t] += u;
        __syncthreads();
    }
    int incl = ss[t];
    int total = ss[SCAN_TPB - 1];

    if (t == 0) {
        if (b == 0) {
            *(volatile int*)&g_incv[0] = total;
            __threadfence();
            *(volatile int*)&g_flag[0] = 2;
            s_excl = 0;
        } else {
            *(volatile int*)&g_aggv[b] = total;
            __threadfence();
            *(volatile int*)&g_flag[b] = 1;
        }
    }
    if (b > 0 && t < 32) {
        int running = 0;
        for (int base = b - 1; base >= 0; base -= 32) {
            int idx = base - t;
            int f;
            do {
                f = (idx >= 0) ? *(volatile int*)&g_flag[idx] : 2;
            } while (__any_sync(0xffffffffu, f == 0));
            __threadfence();
            int val = 0;
            if (idx >= 0)
                val = (f == 2) ? *(volatile int*)&g_incv[idx] : *(volatile int*)&g_aggv[idx];
            unsigned m = __ballot_sync(0xffffffffu, (f == 2) && idx >= 0);
            int firstP = m ? (__ffs(m) - 1) : 32;
            int contrib = (t <= firstP && idx >= 0) ? val : 0;
#pragma unroll
            for (int o = 16; o; o >>= 1) contrib += __shfl_down_sync(0xffffffffu, contrib, o);
            contrib = __shfl_sync(0xffffffffu, contrib, 0);
            running += contrib;
            if (m) break;
        }
        if (t == 0) {
            *(volatile int*)&g_incv[b] = running + total;
            __threadfence();
            *(volatile int*)&g_flag[b] = 2;
            s_excl = running;
        }
    }
    __syncthreads();
    int excl = s_excl + incl - orig;
    if (i < NN) {
        g_rowptr[i] = excl;
        g_cnt[i] = excl;   // scatter cursor
    }
    if (i == 0) g_rowptr[NN] = NE;
}

__global__ void scatter_k(const int* __restrict__ src, const int* __restrict__ dst) {
    int e = blockIdx.x * blockDim.x + threadIdx.x;
    if (e < NE) {
        int p = atomicAdd(&g_cnt[dst[e]], 1);
        g_col[p] = src[e];
    }
}

// ---------------- aggregation: 4 edges/step, uint4 lanes, fp32 accum -----------
__global__ void agg_k(const uint4* __restrict__ hh4, uint4* __restrict__ outh4) {
    int w    = (blockIdx.x * blockDim.x + threadIdx.x) >> 5;
    int lane = threadIdx.x & 31;
    if (w >= NN) return;
    int beg = g_rowptr[w], end = g_rowptr[w + 1];
    int c = lane & 7, es = lane >> 3;
    float acc[8];
#pragma unroll
    for (int k = 0; k < 8; k++) acc[k] = 0.f;
#pragma unroll 2
    for (int e = beg + es; e < end; e += 4) {
        int s = g_col[e];
        uint4 v = hh4[(size_t)s * 8 + c];
        const __half2* p = (const __half2*)&v;
#pragma unroll
        for (int k = 0; k < 4; k++) {
            float2 f = __half22float2(p[k]);
            acc[2 * k]     += f.x;
            acc[2 * k + 1] += f.y;
        }
    }
#pragma unroll
    for (int k = 0; k < 8; k++) {
        acc[k] += __shfl_xor_sync(0xffffffffu, acc[k], 8);
        acc[k] += __shfl_xor_sync(0xffffffffu, acc[k], 16);
    }
    if (lane < 8) {
        __half2 h01 = __floats2half2_rn(acc[0], acc[1]);
        __half2 h23 = __floats2half2_rn(acc[2], acc[3]);
        __half2 h45 = __floats2half2_rn(acc[4], acc[5]);
        __half2 h67 = __floats2half2_rn(acc[6], acc[7]);
        uint4 o;
        o.x = *(uint32_t*)&h01; o.y = *(uint32_t*)&h23;
        o.z = *(uint32_t*)&h45; o.w = *(uint32_t*)&h67;
        outh4[(size_t)w * 8 + c] = o;
    }
}

// ---------------- GRU: fp16 mma.sync, M=32 tile, 3 blocks/SM -------------------
// warp = 16 rows (wid&1) x 16 features (wid>>1) x 3 gate planes, both GEMMs.
// accum 48 regs/thread -> fits 3 blocks/SM (<=84 regs).  SMEM 64512B x3 = 193.5KB
#define ROWB 144
#define OFF_A  0
#define OFF_H  4608
#define OFF_WF 9216
#define OFF_WH 36864
#define GRU_SMEM 64512
#define NTILES ((NN + 31) / 32)   // 3125
#define GRU_GRID 444
#define GRU_TPB 256

#define IDX(p, t) (((p) * 2 + (t)) * 4)

__global__ void __launch_bounds__(GRU_TPB, 3) gru_mma(
    const __half* __restrict__ aggh, const __half* __restrict__ hinh,
    const float* __restrict__ hin, float* __restrict__ hout,
    __half* __restrict__ houth,
    const __half* __restrict__ wf,
    const float* __restrict__ bih, const float* __restrict__ bhh) {
    extern __shared__ __align__(16) char sm[];
    int tid = threadIdx.x, wid = tid >> 5, lane = tid & 31;

    // ---- stage weights ONCE (fp16, [gate][c] rows) ----
    for (int i = tid; i < G3 * 16; i += GRU_TPB) {
        int r = i >> 4, c8 = i & 15;
        uint32_t off = r * ROWB + c8 * 8;
        *(uint2*)(sm + OFF_WF + off) = *(const uint2*)(wf + r * 64 + c8 * 4);
        *(uint2*)(sm + OFF_WH + off) = *(const uint2*)(g_wh + r * 64 + c8 * 4);
    }

    uint32_t sbase = smem_u32(sm);
    int mrow0 = (wid & 1) * 16;        // 2 M-stripes of 16 rows
    int d0 = (wid >> 1) * 16;          // 4 feature groups of 16
    uint32_t aOff = (mrow0 + (lane & 15)) * ROWB + (lane >> 4) * 16;
    uint32_t bRow = (lane >> 4) * 8 + (lane & 7);
    uint32_t bCol = ((lane >> 3) & 1) * 16;

    for (int tile = blockIdx.x; tile < NTILES; tile += GRU_GRID) {
        int n0 = tile * 32;
        __syncthreads();   // previous tile's MMA readers done

        // ---- stage A/H: pure uint4 copy (fp16 already) ----
        {
            int i = tid;                 // 32 rows x 8 chunks = 256 = TPB
            int t = i >> 3, c = i & 7;
            uint4 va = make_uint4(0u, 0u, 0u, 0u), vh = va;
            if (n0 + t < NN) {
                va = ((const uint4*)(aggh + (size_t)(n0 + t) * HD))[c];
                vh = ((const uint4*)(hinh + (size_t)(n0 + t) * HD))[c];
            }
            uint32_t off = t * ROWB + c * 16;
            *(uint4*)(sm + OFF_A + off) = va;
            *(uint4*)(sm + OFF_H + off) = vh;
        }
        __syncthreads();

        // ---- fp16 GEMMs: 3 planes x n16 per warp, both gi and gh ----
        float dgi[24], dgh[24];
#pragma unroll
        for (int q = 0; q < 24; q++) { dgi[q] = 0.f; dgh[q] = 0.f; }

#pragma unroll
        for (int ks = 0; ks < 4; ks++) {
            uint32_t kb = ks * 32;
            uint32_t aF[4], hF[4];
            ldm4(aF, sbase + OFF_A + aOff + kb);
            ldm4(hF, sbase + OFF_H + aOff + kb);
#pragma unroll
            for (int p = 0; p < 3; p++) {
                uint32_t bo = (p * 64 + d0 + bRow) * ROWB + bCol + kb;
                uint32_t bF[4], bG[4];
                ldm4(bF, sbase + OFF_WF + bo);
                ldm4(bG, sbase + OFF_WH + bo);
                mma16816(dgi + IDX(p, 0), aF, bF);
                mma16816(dgi + IDX(p, 1), aF, bF + 2);
                mma16816(dgh + IDX(p, 0), hF, bG);
                mma16816(dgh + IDX(p, 1), hF, bG + 2);
            }
        }

        // ---- register epilogue ----
#pragma unroll
        for (int t = 0; t < 2; t++) {
            int dE = d0 + t * 8 + (lane & 3) * 2;
            float2 bi_r = *(const float2*)(bih + dE);
            float2 bh_r = *(const float2*)(bhh + dE);
            float2 bi_z = *(const float2*)(bih + 64 + dE);
            float2 bh_z = *(const float2*)(bhh + 64 + dE);
            float2 bi_n = *(const float2*)(bih + 128 + dE);
            float2 bh_n = *(const float2*)(bhh + 128 + dE);
            float brz[2] = {bi_r.x + bh_r.x, bi_r.y + bh_r.y};
            float bzz[2] = {bi_z.x + bh_z.x, bi_z.y + bh_z.y};
            float bnn[2] = {bi_n.x, bi_n.y};
            float bhn[2] = {bh_n.x, bh_n.y};
#pragma unroll
            for (int rh = 0; rh < 2; rh++) {
                int row = mrow0 + (lane >> 2) + rh * 8;
                if (n0 + row >= NN) continue;
                float2 hpv = *(const float2*)(hin + (size_t)(n0 + row) * HD + dE);
                float hpa[2] = {hpv.x, hpv.y};
                float outv[2];
#pragma unroll
                for (int j = 0; j < 2; j++) {
                    int q = rh * 2 + j;
                    float ar = dgi[IDX(0, t) + q] + dgh[IDX(0, t) + q] + brz[j];
                    float az = dgi[IDX(1, t) + q] + dgh[IDX(1, t) + q] + bzz[j];
                    float r = 1.f / (1.f + __expf(-ar));
                    float z = 1.f / (1.f + __expf(-az));
                    float xarg = dgi[IDX(2, t) + q] + bnn[j] +
                                 r * (dgh[IDX(2, t) + q] + bhn[j]);
                    float nn = 1.f - 2.f / (__expf(2.f * xarg) + 1.f);  // tanh
                    outv[j] = (1.f - z) * nn + z * hpa[j];
                }
                size_t gidx = (size_t)(n0 + row) * HD + dE;
                *(float2*)(hout + gidx) = make_float2(outv[0], outv[1]);
                *(__half2*)(houth + gidx) = __floats2half2_rn(outv[0], outv[1]);
            }
        }
    }
}

// ---------------- pooling: batch sorted -> run-length accumulate ---------------
__global__ void pool_k(const float* __restrict__ h, const int* __restrict__ batch,
                       float* __restrict__ out) {
    int d = threadIdx.x;
    int n0 = blockIdx.x * 128;
    int nend = min(n0 + 128, NN);
    if (n0 >= NN) return;
    float acc = 0.f;
    int cur = batch[n0];
    for (int n = n0; n < nend; n++) {
        int b = batch[n];
        if (b != cur) {
            atomicAdd(&out[cur * HD + d], acc);
            acc = 0.f;
            cur = b;
        }
        acc += h[(size_t)n * HD + d];
    }
    atomicAdd(&out[cur * HD + d], acc);
}

// ---------------- launch --------------------------------------------------------
extern "C" void kernel_launch(void* const* d_in, const int* in_sizes, int n_in,
                              void* d_out, int out_size) {
    const float* x    = (const float*)d_in[0];
    const int*   ei   = (const int*)d_in[1];
    const int*   batch= (const int*)d_in[2];
    const float* W    = (const float*)d_in[3];
    const float* Wih  = (const float*)d_in[4];
    const float* Whh  = (const float*)d_in[5];
    const float* bih  = (const float*)d_in[6];
    const float* bhh  = (const float*)d_in[7];
    float* out = (float*)d_out;
    const int* src = ei;
    const int* dst = ei + NE;

    void *h0p, *h1p, *xhp, *hh0p, *hh1p, *agghp, *wfp;
    cudaGetSymbolAddress(&h0p, g_h0);
    cudaGetSymbolAddress(&h1p, g_h1);
    cudaGetSymbolAddress(&xhp, g_xh);
    cudaGetSymbolAddress(&hh0p, g_hh0);
    cudaGetSymbolAddress(&hh1p, g_hh1);
    cudaGetSymbolAddress(&agghp, g_aggh);
    cudaGetSymbolAddress(&wfp, g_wf);

    cudaFuncSetAttribute(gru_mma, cudaFuncAttributeMaxDynamicSharedMemorySize, GRU_SMEM);

    prep_k<<<(NN * HD + 255) / 256, 256>>>(W, Wih, Whh, x, out);
    hist_k<<<(NE + 255) / 256, 256>>>(dst);
    scan_k<<<SCAN_BLKS, SCAN_TPB>>>();
    scatter_k<<<(NE + 255) / 256, 256>>>(src, dst);

    const float*  hin  = x;
    const __half* hinh = (const __half*)xhp;
    for (int l = 0; l < NLAY; l++) {
        float*  hout  = (l & 1) ? (float*)h0p : (float*)h1p;
        __half* houth = (l & 1) ? (__half*)hh0p : (__half*)hh1p;
        agg_k<<<(NN * 32 + 255) / 256, 256>>>((const uint4*)hinh, (uint4*)agghp);
        gru_mma<<<GRU_GRID, GRU_TPB, GRU_SMEM>>>(
            (const __half*)agghp, hinh, hin, hout, houth,
            (const __half*)wfp + (size_t)l * G3 * HD,
            bih, bhh);
        hin = hout;
        hinh = houth;
    }
    pool_k<<<(NN + 127) / 128, 64>>>(hin, batch, out);
}

// round 16
// speedup vs baseline: 1.6031x; 1.0630x over previous
#include <cuda_runtime.h>
#include <cuda_fp16.h>
#include <math.h>
#include <cstdint>

#define NN   100000
#define NE   1600000
#define HD   64
#define NG   256
#define NLAY 3
#define G3   192   // 3*HD

#define SCAN_TPB  512
#define SCAN_BLKS ((NN + SCAN_TPB - 1) / SCAN_TPB)   // 196

// ---------------- scratch (device globals; no allocation allowed) -------------
__device__ float  g_h0[NN * HD];
__device__ float  g_h1[NN * HD];
__device__ __half g_xh[NN * HD];      // fp16 mirror of x
__device__ __half g_hh0[NN * HD];     // fp16 mirror of h (ping/pong)
__device__ __half g_hh1[NN * HD];
__device__ __half g_aggh[NN * HD];    // fp16 aggregation result
__device__ int   g_rowptr[NN + 1];
__device__ int   g_cnt[NN];
__device__ int   g_aggv[SCAN_BLKS];
__device__ int   g_incv[SCAN_BLKS];
__device__ int   g_flag[SCAN_BLKS];
__device__ int   g_col[NE];
__device__ __half g_wf[NLAY * G3 * HD];   // fp16 fused W@Wih^T, [l][gate][c]
__device__ __half g_wh[G3 * HD];          // fp16 W_hh

// ---------------- host-side stream/event resources (static init, pre-checkpoint)
static cudaStream_t g_s1;
static cudaEvent_t  g_evA, g_evB;
static struct GInit {
    GInit() {
        cudaStreamCreateWithFlags(&g_s1, cudaStreamNonBlocking);
        cudaEventCreateWithFlags(&g_evA, cudaEventDisableTiming);
        cudaEventCreateWithFlags(&g_evB, cudaEventDisableTiming);
    }
} g_ginit;

// ---------------- ptx helpers (baseline ISA only: ldmatrix + mma.sync) --------
__device__ __forceinline__ uint32_t smem_u32(const void* p) {
    uint32_t a;
    asm("{ .reg .u64 t; cvta.to.shared.u64 t, %1; cvt.u32.u64 %0, t; }" : "=r"(a) : "l"(p));
    return a;
}
__device__ __forceinline__ void ldm4(uint32_t* r, uint32_t addr) {
    asm volatile("ldmatrix.sync.aligned.m8n8.x4.shared.b16 {%0,%1,%2,%3}, [%4];"
                 : "=r"(r[0]), "=r"(r[1]), "=r"(r[2]), "=r"(r[3]) : "r"(addr));
}
__device__ __forceinline__ void mma16816(float* d, const uint32_t* a, const uint32_t* b) {
    asm volatile(
        "mma.sync.aligned.m16n8k16.row.col.f32.f16.f16.f32 "
        "{%0,%1,%2,%3}, {%4,%5,%6,%7}, {%8,%9}, {%0,%1,%2,%3};"
        : "+f"(d[0]), "+f"(d[1]), "+f"(d[2]), "+f"(d[3])
        : "r"(a[0]), "r"(a[1]), "r"(a[2]), "r"(a[3]), "r"(b[0]), "r"(b[1]));
}

// ---------------- zero: counters + flags + output ------------------------------
__global__ void zero_k(float* __restrict__ out) {
    int tid = blockIdx.x * blockDim.x + threadIdx.x;
    if (tid < NN) g_cnt[tid] = 0;
    if (tid < SCAN_BLKS) g_flag[tid] = 0;
    if (tid < NG * HD) out[tid] = 0.f;
}

// ---------------- prep: weight fusion + fp16 casts (no zeroing) ----------------
__global__ void prep_k(const float* __restrict__ W, const float* __restrict__ Wih,
                       const float* __restrict__ Whh, const float* __restrict__ x) {
    int tid = blockIdx.x * blockDim.x + threadIdx.x;
    if (tid < NN * HD) g_xh[tid] = __float2half(x[tid]);
    if (tid < NLAY * G3 * HD) {
        int c = tid & (HD - 1);
        int j = (tid >> 6) % G3;
        int l = tid / (G3 * HD);
        const float* wrow = W + (l * HD + c) * HD;
        const float* irow = Wih + j * HD;
        float s = 0.f;
#pragma unroll
        for (int k = 0; k < HD; k++) s = fmaf(wrow[k], irow[k], s);
        g_wf[tid] = __float2half(s);
    }
    if (tid < G3 * HD) g_wh[tid] = __float2half(Whh[tid]);
}

// ---------------- CSR build (4 edges/thread) -----------------------------------
__global__ void hist_k(const int4* __restrict__ dst4) {
    int i = blockIdx.x * blockDim.x + threadIdx.x;
    if (i < NE / 4) {
        int4 d = dst4[i];
        atomicAdd(&g_cnt[d.x], 1);
        atomicAdd(&g_cnt[d.y], 1);
        atomicAdd(&g_cnt[d.z], 1);
        atomicAdd(&g_cnt[d.w], 1);
    }
}

// single-pass decoupled-lookback scan (196 blocks, all resident)
__global__ void scan_k() {
    __shared__ int ss[SCAN_TPB];
    __shared__ int s_excl;
    int t = threadIdx.x, b = blockIdx.x;
    int i = b * SCAN_TPB + t;
    int orig = (i < NN) ? g_cnt[i] : 0;
    ss[t] = orig;
    __syncthreads();
#pragma unroll
    for (int off = 1; off < SCAN_TPB; off <<= 1) {
        int u = (t >= off) ? ss[t - off] : 0;
        __syncthreads();
        ss[t] += u;
        __syncthreads();
    }
    int incl = ss[t];
    int total = ss[SCAN_TPB - 1];

    if (t == 0) {
        if (b == 0) {
            *(volatile int*)&g_incv[0] = total;
            __threadfence();
            *(volatile int*)&g_flag[0] = 2;
            s_excl = 0;
        } else {
            *(volatile int*)&g_aggv[b] = total;
            __threadfence();
            *(volatile int*)&g_flag[b] = 1;
        }
    }
    if (b > 0 && t < 32) {
        int running = 0;
        for (int base = b - 1; base >= 0; base -= 32) {
            int idx = base - t;
            int f;
            do {
                f = (idx >= 0) ? *(volatile int*)&g_flag[idx] : 2;
            } while (__any_sync(0xffffffffu, f == 0));
            __threadfence();
            int val = 0;
            if (idx >= 0)
                val = (f == 2) ? *(volatile int*)&g_incv[idx] : *(volatile int*)&g_aggv[idx];
            unsigned m = __ballot_sync(0xffffffffu, (f == 2) && idx >= 0);
            int firstP = m ? (__ffs(m) - 1) : 32;
            int contrib = (t <= firstP && idx >= 0) ? val : 0;
#pragma unroll
            for (int o = 16; o; o >>= 1) contrib += __shfl_down_sync(0xffffffffu, contrib, o);
            contrib = __shfl_sync(0xffffffffu, contrib, 0);
            running += contrib;
            if (m) break;
        }
        if (t == 0) {
            *(volatile int*)&g_incv[b] = running + total;
            __threadfence();
            *(volatile int*)&g_flag[b] = 2;
            s_excl = running;
        }
    }
    __syncthreads();
    int excl = s_excl + incl - orig;
    if (i < NN) {
        g_rowptr[i] = excl;
        g_cnt[i] = excl;   // scatter cursor
    }
    if (i == 0) g_rowptr[NN] = NE;
}

__global__ void scatter_k(const int4* __restrict__ src4, const int4* __restrict__ dst4) {
    int i = blockIdx.x * blockDim.x + threadIdx.x;
    if (i < NE / 4) {
        int4 d = dst4[i];
        int4 s = src4[i];
        g_col[atomicAdd(&g_cnt[d.x], 1)] = s.x;
        g_col[atomicAdd(&g_cnt[d.y], 1)] = s.y;
        g_col[atomicAdd(&g_cnt[d.z], 1)] = s.z;
        g_col[atomicAdd(&g_cnt[d.w], 1)] = s.w;
    }
}

// ---------------- aggregation: 4 edges/step, uint4 lanes, fp32 accum -----------
__global__ void agg_k(const uint4* __restrict__ hh4, uint4* __restrict__ outh4) {
    int w    = (blockIdx.x * blockDim.x + threadIdx.x) >> 5;
    int lane = threadIdx.x & 31;
    if (w >= NN) return;
    int beg = g_rowptr[w], end = g_rowptr[w + 1];
    int c = lane & 7, es = lane >> 3;
    float acc[8];
#pragma unroll
    for (int k = 0; k < 8; k++) acc[k] = 0.f;
#pragma unroll 2
    for (int e = beg + es; e < end; e += 4) {
        int s = g_col[e];
        uint4 v = hh4[(size_t)s * 8 + c];
        const __half2* p = (const __half2*)&v;
#pragma unroll
        for (int k = 0; k < 4; k++) {
            float2 f = __half22float2(p[k]);
            acc[2 * k]     += f.x;
            acc[2 * k + 1] += f.y;
        }
    }
#pragma unroll
    for (int k = 0; k < 8; k++) {
        acc[k] += __shfl_xor_sync(0xffffffffu, acc[k], 8);
        acc[k] += __shfl_xor_sync(0xffffffffu, acc[k], 16);
    }
    if (lane < 8) {
        __half2 h01 = __floats2half2_rn(acc[0], acc[1]);
        __half2 h23 = __floats2half2_rn(acc[2], acc[3]);
        __half2 h45 = __floats2half2_rn(acc[4], acc[5]);
        __half2 h67 = __floats2half2_rn(acc[6], acc[7]);
        uint4 o;
        o.x = *(uint32_t*)&h01; o.y = *(uint32_t*)&h23;
        o.z = *(uint32_t*)&h45; o.w = *(uint32_t*)&h67;
        outh4[(size_t)w * 8 + c] = o;
    }
}

// ---------------- GRU: fp16 mma.sync, M=32 tile, 3 blocks/SM -------------------
#define ROWB 144
#define OFF_A  0
#define OFF_H  4608
#define OFF_WF 9216
#define OFF_WH 36864
#define GRU_SMEM 64512
#define NTILES ((NN + 31) / 32)   // 3125
#define GRU_GRID 444
#define GRU_TPB 256

#define IDX(p, t) (((p) * 2 + (t)) * 4)

__global__ void __launch_bounds__(GRU_TPB, 3) gru_mma(
    const __half* __restrict__ aggh, const __half* __restrict__ hinh,
    const float* __restrict__ hin, float* __restrict__ hout,
    __half* __restrict__ houth, int store_h,
    const __half* __restrict__ wf,
    const float* __restrict__ bih, const float* __restrict__ bhh) {
    extern __shared__ __align__(16) char sm[];
    int tid = threadIdx.x, wid = tid >> 5, lane = tid & 31;

    // ---- stage weights ONCE (fp16, [gate][c] rows) ----
    for (int i = tid; i < G3 * 16; i += GRU_TPB) {
        int r = i >> 4, c8 = i & 15;
        uint32_t off = r * ROWB + c8 * 8;
        *(uint2*)(sm + OFF_WF + off) = *(const uint2*)(wf + r * 64 + c8 * 4);
        *(uint2*)(sm + OFF_WH + off) = *(const uint2*)(g_wh + r * 64 + c8 * 4);
    }

    uint32_t sbase = smem_u32(sm);
    int mrow0 = (wid & 1) * 16;        // 2 M-stripes of 16 rows
    int d0 = (wid >> 1) * 16;          // 4 feature groups of 16
    uint32_t aOff = (mrow0 + (lane & 15)) * ROWB + (lane >> 4) * 16;
    uint32_t bRow = (lane >> 4) * 8 + (lane & 7);
    uint32_t bCol = ((lane >> 3) & 1) * 16;

    for (int tile = blockIdx.x; tile < NTILES; tile += GRU_GRID) {
        int n0 = tile * 32;
        __syncthreads();   // previous tile's MMA readers done

        // ---- stage A/H: pure uint4 copy (fp16 already) ----
        {
            int i = tid;                 // 32 rows x 8 chunks = 256 = TPB
            int t = i >> 3, c = i & 7;
            uint4 va = make_uint4(0u, 0u, 0u, 0u), vh = va;
            if (n0 + t < NN) {
                va = ((const uint4*)(aggh + (size_t)(n0 + t) * HD))[c];
                vh = ((const uint4*)(hinh + (size_t)(n0 + t) * HD))[c];
            }
            uint32_t off = t * ROWB + c * 16;
            *(uint4*)(sm + OFF_A + off) = va;
            *(uint4*)(sm + OFF_H + off) = vh;
        }
        __syncthreads();

        // ---- fp16 GEMMs: 3 planes x n16 per warp, both gi and gh ----
        float dgi[24], dgh[24];
#pragma unroll
        for (int q = 0; q < 24; q++) { dgi[q] = 0.f; dgh[q] = 0.f; }

#pragma unroll
        for (int ks = 0; ks < 4; ks++) {
            uint32_t kb = ks * 32;
            uint32_t aF[4], hF[4];
            ldm4(aF, sbase + OFF_A + aOff + kb);
            ldm4(hF, sbase + OFF_H + aOff + kb);
#pragma unroll
            for (int p = 0; p < 3; p++) {
                uint32_t bo = (p * 64 + d0 + bRow) * ROWB + bCol + kb;
                uint32_t bF[4], bG[4];
                ldm4(bF, sbase + OFF_WF + bo);
                ldm4(bG, sbase + OFF_WH + bo);
                mma16816(dgi + IDX(p, 0), aF, bF);
                mma16816(dgi + IDX(p, 1), aF, bF + 2);
                mma16816(dgh + IDX(p, 0), hF, bG);
                mma16816(dgh + IDX(p, 1), hF, bG + 2);
            }
        }

        // ---- register epilogue ----
#pragma unroll
        for (int t = 0; t < 2; t++) {
            int dE = d0 + t * 8 + (lane & 3) * 2;
            float2 bi_r = *(const float2*)(bih + dE);
            float2 bh_r = *(const float2*)(bhh + dE);
            float2 bi_z = *(const float2*)(bih + 64 + dE);
            float2 bh_z = *(const float2*)(bhh + 64 + dE);
            float2 bi_n = *(const float2*)(bih + 128 + dE);
            float2 bh_n = *(const float2*)(bhh + 128 + dE);
            float brz[2] = {bi_r.x + bh_r.x, bi_r.y + bh_r.y};
            float bzz[2] = {bi_z.x + bh_z.x, bi_z.y + bh_z.y};
            float bnn[2] = {bi_n.x, bi_n.y};
            float bhn[2] = {bh_n.x, bh_n.y};
#pragma unroll
            for (int rh = 0; rh < 2; rh++) {
                int row = mrow0 + (lane >> 2) + rh * 8;
                if (n0 + row >= NN) continue;
                float2 hpv = *(const float2*)(hin + (size_t)(n0 + row) * HD + dE);
                float hpa[2] = {hpv.x, hpv.y};
                float outv[2];
#pragma unroll
                for (int j = 0; j < 2; j++) {
                    int q = rh * 2 + j;
                    float ar = dgi[IDX(0, t) + q] + dgh[IDX(0, t) + q] + brz[j];
                    float az = dgi[IDX(1, t) + q] + dgh[IDX(1, t) + q] + bzz[j];
                    float r = 1.f / (1.f + __expf(-ar));
                    float z = 1.f / (1.f + __expf(-az));
                    float xarg = dgi[IDX(2, t) + q] + bnn[j] +
                                 r * (dgh[IDX(2, t) + q] + bhn[j]);
                    float nn = 1.f - 2.f / (__expf(2.f * xarg) + 1.f);  // tanh
                    outv[j] = (1.f - z) * nn + z * hpa[j];
                }
                size_t gidx = (size_t)(n0 + row) * HD + dE;
                *(float2*)(hout + gidx) = make_float2(outv[0], outv[1]);
                if (store_h)
                    *(__half2*)(houth + gidx) = __floats2half2_rn(outv[0], outv[1]);
            }
        }
    }
}

// ---------------- pooling: batch sorted -> run-length accumulate ---------------
__global__ void pool_k(const float* __restrict__ h, const int* __restrict__ batch,
                       float* __restrict__ out) {
    int d = threadIdx.x;
    int n0 = blockIdx.x * 128;
    int nend = min(n0 + 128, NN);
    if (n0 >= NN) return;
    float acc = 0.f;
    int cur = batch[n0];
    for (int n = n0; n < nend; n++) {
        int b = batch[n];
        if (b != cur) {
            atomicAdd(&out[cur * HD + d], acc);
            acc = 0.f;
            cur = b;
        }
        acc += h[(size_t)n * HD + d];
    }
    atomicAdd(&out[cur * HD + d], acc);
}

// ---------------- launch --------------------------------------------------------
extern "C" void kernel_launch(void* const* d_in, const int* in_sizes, int n_in,
                              void* d_out, int out_size) {
    const float* x    = (const float*)d_in[0];
    const int*   ei   = (const int*)d_in[1];
    const int*   batch= (const int*)d_in[2];
    const float* W    = (const float*)d_in[3];
    const float* Wih  = (const float*)d_in[4];
    const float* Whh  = (const float*)d_in[5];
    const float* bih  = (const float*)d_in[6];
    const float* bhh  = (const float*)d_in[7];
    float* out = (float*)d_out;
    const int* src = ei;
    const int* dst = ei + NE;

    void *h0p, *h1p, *xhp, *hh0p, *hh1p, *agghp, *wfp;
    cudaGetSymbolAddress(&h0p, g_h0);
    cudaGetSymbolAddress(&h1p, g_h1);
    cudaGetSymbolAddress(&xhp, g_xh);
    cudaGetSymbolAddress(&hh0p, g_hh0);
    cudaGetSymbolAddress(&hh1p, g_hh1);
    cudaGetSymbolAddress(&agghp, g_aggh);
    cudaGetSymbolAddress(&wfp, g_wf);

    cudaFuncSetAttribute(gru_mma, cudaFuncAttributeMaxDynamicSharedMemorySize, GRU_SMEM);

    // zero counters first (main stream), then fork CSR chain to side stream
    zero_k<<<(NN + 255) / 256, 256>>>(out);
    cudaEventRecord(g_evA, 0);
    cudaStreamWaitEvent(g_s1, g_evA, 0);
    hist_k<<<(NE / 4 + 255) / 256, 256, 0, g_s1>>>((const int4*)dst);
    scan_k<<<SCAN_BLKS, SCAN_TPB, 0, g_s1>>>();
    scatter_k<<<(NE / 4 + 255) / 256, 256, 0, g_s1>>>((const int4*)src, (const int4*)dst);
    cudaEventRecord(g_evB, g_s1);

    // concurrent with CSR build: weight fusion + x cast on main stream
    prep_k<<<(NN * HD + 255) / 256, 256>>>(W, Wih, Whh, x);

    // join CSR branch before layer loop
    cudaStreamWaitEvent(0, g_evB, 0);

    const float*  hin  = x;
    const __half* hinh = (const __half*)xhp;
    for (int l = 0; l < NLAY; l++) {
        float*  hout  = (l & 1) ? (float*)h0p : (float*)h1p;
        __half* houth = (l & 1) ? (__half*)hh0p : (__half*)hh1p;
        agg_k<<<(NN * 32 + 255) / 256, 256>>>((const uint4*)hinh, (uint4*)agghp);
        gru_mma<<<GRU_GRID, GRU_TPB, GRU_SMEM>>>(
            (const __half*)agghp, hinh, hin, hout, houth, (l < NLAY - 1) ? 1 : 0,
            (const __half*)wfp + (size_t)l * G3 * HD,
            bih, bhh);
        hin = hout;
        hinh = houth;
    }
    pool_k<<<(NN + 127) / 128, 64>>>(hin, batch, out);
}